// round 16
// baseline (speedup 1.0000x reference)
#include <cuda_runtime.h>
#include <math.h>

#define T_LEN      220500
#define NCH        64
#define CHUNK      84
#define SUBA       40                 // sub-chunk A: samples 0..39
#define SUBB       44                 // sub-chunk B: samples 40..83
#define NCHUNK_CH  2625                // 220500 / 84
#define NCHUNK_TOT 168000              // 64 * 2625
#define TOTAL_F4   3528000             // 14,112,000 / 4
#define BT         128
#define NW         (BT / 32)
#define TILE       (BT * CHUNK)        // 10752 floats = 43008 B
#define F4PB       (TILE / 4)          // 2688
#define NBLK       ((NCHUNK_TOT + BT - 1) / BT)   // 1313
#define WIN        21                  // reset-block gap is exactly 20-21

typedef unsigned long long u64;

// ---- packed f32x2 helpers (sm_103a FFMA2 path) ----
__device__ __forceinline__ u64 fma2(u64 a, u64 b, u64 c) {
    u64 d; asm("fma.rn.f32x2 %0, %1, %2, %3;" : "=l"(d) : "l"(a), "l"(b), "l"(c)); return d;
}
__device__ __forceinline__ u64 mul2(u64 a, u64 b) {
    u64 d; asm("mul.rn.f32x2 %0, %1, %2;" : "=l"(d) : "l"(a), "l"(b)); return d;
}
__device__ __forceinline__ u64 pack2(float lo, float hi) {
    u64 d; asm("mov.b64 %0, {%1, %2};" : "=l"(d) : "f"(lo), "f"(hi)); return d;
}
__device__ __forceinline__ void unpack2(u64 v, float& lo, float& hi) {
    asm("mov.b64 {%0, %1}, %2;" : "=f"(lo), "=f"(hi) : "l"(v));
}

// published per-block aggregate: [0]=(La,Lb,Lc,Ld) [1]=(Lp,Lq,Hp,Hq) [2]=(Ha,Hb,Hc,Hd)
__device__ float4 g_agg[NBLK][3];
__device__ int    g_flag[NBLK];    // statically zero-init; self-resetting per replay
__device__ int    g_cnt[NBLK];     // read-counters; self-resetting per replay

struct Map { float a, b, c, d, p, q; };   // s -> [a b; c d] s + (p,q)

__device__ __forceinline__ Map mapIdent() { Map m = {1.f,0.f,0.f,1.f,0.f,0.f}; return m; }
// hi applied AFTER lo
__device__ __forceinline__ Map mapCompose(const Map& hi, const Map& lo) {
    Map r;
    r.a = fmaf(hi.a, lo.a, hi.b * lo.c);
    r.b = fmaf(hi.a, lo.b, hi.b * lo.d);
    r.c = fmaf(hi.c, lo.a, hi.d * lo.c);
    r.d = fmaf(hi.c, lo.b, hi.d * lo.d);
    r.p = fmaf(hi.a, lo.p, fmaf(hi.b, lo.q, hi.p));
    r.q = fmaf(hi.c, lo.p, fmaf(hi.d, lo.q, hi.q));
    return r;
}
__device__ __forceinline__ float2 mapApply(const Map& m, float vx, float vy) {
    return make_float2(fmaf(m.a, vx, fmaf(m.b, vy, m.p)),
                       fmaf(m.c, vx, fmaf(m.d, vy, m.q)));
}
__device__ __forceinline__ Map mapShflUp(const Map& m, int d) {
    Map r;
    r.a = __shfl_up_sync(0xffffffffu, m.a, d);
    r.b = __shfl_up_sync(0xffffffffu, m.b, d);
    r.c = __shfl_up_sync(0xffffffffu, m.c, d);
    r.d = __shfl_up_sync(0xffffffffu, m.d, d);
    r.p = __shfl_up_sync(0xffffffffu, m.p, d);
    r.q = __shfl_up_sync(0xffffffffu, m.q, d);
    return r;
}

// packed biquad step, parametric state (two independent chains per thread)
#define BSTEP2S(xk, ok, s1, s2, xm1, xm2) {                      \
    u64 xk2 = pack2((xk), (xk));                                 \
    u64 ff  = fma2(cb0, xk2, fma2(cb1, xm1, mul2(cb2, xm2)));    \
    u64 yy  = fma2(cn1, s1, fma2(cn2, s2, ff));                  \
    float yL, yH; unpack2(yy, yL, yH);                           \
    (ok) = yL - yH;                                              \
    s2 = s1; s1 = yy; xm2 = xm1; xm1 = xk2; }

// packed homogeneous correction step, parametric state
#define CSTEP2S(y0v, ov, cd1, cd2) {                             \
    u64 cd = fma2(cn1, cd1, mul2(cn2, cd2));                     \
    float cc, dd; unpack2(cd, cc, dd);                           \
    (ov) = ((y0v) + cc) - dd;                                    \
    cd2 = cd1; cd1 = cd; }

__global__ __launch_bounds__(BT, 5)
void fused_kernel(const float* __restrict__ x, float* __restrict__ out,
                  const int* __restrict__ sr_p,
                  const float* __restrict__ cl_p,
                  const float* __restrict__ ch_p) {
    __shared__ float  sbuf[TILE];
    __shared__ float  scoef[10];
    __shared__ float4 sAE[4];  // [0..1]=A^40 rows (uL,vL,uH,vH); [2..3]=A^44 rows
    __shared__ Map    sWarpL[NW], sWarpH[NW];
    __shared__ float4 sPred[WIN][3];
    __shared__ float4 sVin;

    int t   = threadIdx.x;
    int bid = blockIdx.x;
    bool fullBlk = (bid < NBLK - 1);

    // ---- stage tile coalesced ----
    size_t base4 = (size_t)bid * F4PB;
    const float4* xg4 = (const float4*)x;
    float4* s4 = (float4*)sbuf;
    if (fullBlk) {
#pragma unroll
        for (int i = 0; i < F4PB / BT; i++)
            s4[t + i * BT] = xg4[base4 + t + (size_t)i * BT];
    } else {
#pragma unroll
        for (int i = 0; i < F4PB / BT; i++) {
            size_t idx = base4 + t + (size_t)i * BT;
            if (idx < TOTAL_F4) s4[t + i * BT] = xg4[idx];
        }
    }

    // ---- thread 0: coefficients (overlaps staging latency) ----
    if (t == 0) {
        int iv = *sr_p;
        float sr = (iv > 0 && iv < 100000000) ? (float)iv : __int_as_float(iv);
        const float Q = 0.707f;
        {
            float w0 = 2.0f * 3.14159265358979323846f * (*cl_p) / sr;
            float c  = cosf(w0);
            float al = sinf(w0) / (2.0f * Q);
            float a0 = 1.0f + al;
            scoef[0] = ((1.0f - c) * 0.5f) / a0;
            scoef[1] = (1.0f - c) / a0;
            scoef[2] = scoef[0];
            scoef[3] = (-2.0f * c) / a0;
            scoef[4] = (1.0f - al) / a0;
        }
        {
            float w0 = 2.0f * 3.14159265358979323846f * (*ch_p) / sr;
            float c  = cosf(w0);
            float al = sinf(w0) / (2.0f * Q);
            float a0 = 1.0f + al;
            scoef[5] = ((1.0f + c) * 0.5f) / a0;
            scoef[6] = -(1.0f + c) / a0;
            scoef[7] = scoef[5];
            scoef[8] = (-2.0f * c) / a0;
            scoef[9] = (1.0f - al) / a0;
        }
    }
    __syncthreads();   // B1

    float bL0 = scoef[0], bL1 = scoef[1], bL2 = scoef[2];
    float nL1 = -scoef[3], nL2 = -scoef[4];
    float bH0 = scoef[5], bH1 = scoef[6], bH2 = scoef[7];
    float nH1 = -scoef[8], nH2 = -scoef[9];

    u64 cb0 = pack2(bL0, bH0), cb1 = pack2(bL1, bH1), cb2 = pack2(bL2, bH2);
    u64 cn1 = pack2(nL1, nH1), cn2 = pack2(nL2, nH2);

    int  g       = bid * BT + t;
    bool valid   = g < NCHUNK_TOT;
    bool resetCk = valid && (g % NCHUNK_CH) == 0;

    // FIR history for sub-chunk A from global (L1-hot after staging)
    float hx1 = 0.f, hx2 = 0.f;
    if (valid && !resetCk) {
        size_t s0 = (size_t)g * CHUNK;
        hx1 = __ldg(x + s0 - 1);
        hx2 = __ldg(x + s0 - 2);
    }

    // ---- homogeneous basis: A^40 and A^44 from one 44-step run (threads 0-3) ----
    if (t < 4) {
        float na1 = (t < 2) ? nL1 : nH1;
        float na2 = (t < 2) ? nL2 : nH2;
        float y1 = (t & 1) ? 0.f : 1.f;
        float y2 = (t & 1) ? 1.f : 0.f;
#pragma unroll 1
        for (int n = 0; n < SUBB; n++) {
            float y = fmaf(na1, y1, na2 * y2);
            y2 = y1; y1 = y;
            if (n == SUBA - 1) {
                ((float*)&sAE[0])[t] = y1;   // y[39]
                ((float*)&sAE[1])[t] = y2;   // y[38]
            }
        }
        ((float*)&sAE[2])[t] = y1;   // y[43]
        ((float*)&sAE[3])[t] = y2;   // y[42]
    }

    // ---- pass A: TWO independent zero-init recurrences per thread (ILP-2) ----
    float la1, la2, ha1, ha2, lb1, lb2, hb1, hb2;
    {
        u64 sa1 = pack2(0.f, 0.f), sa2 = sa1, sb1 = sa1, sb2 = sa1;
        u64 xa1 = pack2(hx1, hx1), xa2 = pack2(hx2, hx2);
        float* cb = sbuf + t * CHUNK;
        float xbh1 = 0.f, xbh2 = 0.f;
        if (valid) { xbh1 = cb[SUBA - 1]; xbh2 = cb[SUBA - 2]; }  // B history (pre-overwrite)
        u64 xb1 = pack2(xbh1, xbh1), xb2 = pack2(xbh2, xbh2);
        if (valid) {
#pragma unroll
            for (int k = 0; k < SUBA; k += 4) {
                float4 xa = *reinterpret_cast<const float4*>(cb + k);
                float4 xb = *reinterpret_cast<const float4*>(cb + SUBA + k);
                float4 oa, ob;
                BSTEP2S(xa.x, oa.x, sa1, sa2, xa1, xa2);
                BSTEP2S(xb.x, ob.x, sb1, sb2, xb1, xb2);
                BSTEP2S(xa.y, oa.y, sa1, sa2, xa1, xa2);
                BSTEP2S(xb.y, ob.y, sb1, sb2, xb1, xb2);
                BSTEP2S(xa.z, oa.z, sa1, sa2, xa1, xa2);
                BSTEP2S(xb.z, ob.z, sb1, sb2, xb1, xb2);
                BSTEP2S(xa.w, oa.w, sa1, sa2, xa1, xa2);
                BSTEP2S(xb.w, ob.w, sb1, sb2, xb1, xb2);
                *reinterpret_cast<float4*>(cb + k) = oa;
                *reinterpret_cast<float4*>(cb + SUBA + k) = ob;
            }
            // B tail: samples 80..83
            float4 xb = *reinterpret_cast<const float4*>(cb + 2 * SUBA);
            float4 ob;
            BSTEP2S(xb.x, ob.x, sb1, sb2, xb1, xb2);
            BSTEP2S(xb.y, ob.y, sb1, sb2, xb1, xb2);
            BSTEP2S(xb.z, ob.z, sb1, sb2, xb1, xb2);
            BSTEP2S(xb.w, ob.w, sb1, sb2, xb1, xb2);
            *reinterpret_cast<float4*>(cb + 2 * SUBA) = ob;
        }
        unpack2(sa1, la1, ha1);
        unpack2(sa2, la2, ha2);
        unpack2(sb1, lb1, hb1);
        unpack2(sb2, lb2, hb2);
    }
    __syncthreads();   // B2: sAE + pass A complete

    float4 e40a = sAE[0], e40b = sAE[1];   // A^40 rows
    float4 e44a = sAE[2], e44b = sAE[3];   // A^44 rows

    // ---- composite per-thread maps: M = M_B ∘ M_A ----
    Map mL, mH;
    if (!valid) { mL = mapIdent(); mH = mapIdent(); }
    else {
        Map MA_L, MA_H;
        if (resetCk) {
            MA_L.a = MA_L.b = MA_L.c = MA_L.d = 0.f; MA_L.p = la1; MA_L.q = la2;
            MA_H.a = MA_H.b = MA_H.c = MA_H.d = 0.f; MA_H.p = ha1; MA_H.q = ha2;
        } else {
            MA_L.a = e40a.x; MA_L.b = e40a.y; MA_L.c = e40b.x; MA_L.d = e40b.y; MA_L.p = la1; MA_L.q = la2;
            MA_H.a = e40a.z; MA_H.b = e40a.w; MA_H.c = e40b.z; MA_H.d = e40b.w; MA_H.p = ha1; MA_H.q = ha2;
        }
        Map MB_L = { e44a.x, e44a.y, e44b.x, e44b.y, lb1, lb2 };
        Map MB_H = { e44a.z, e44a.w, e44b.z, e44b.w, hb1, hb2 };
        mL = mapCompose(MB_L, MA_L);
        mH = mapCompose(MB_H, MA_H);
    }

    int lane = t & 31, w = t >> 5;
#pragma unroll
    for (int off = 1; off < 32; off <<= 1) {
        Map pL = mapShflUp(mL, off);
        Map pH = mapShflUp(mH, off);
        if (lane >= off) { mL = mapCompose(mL, pL); mH = mapCompose(mH, pH); }
    }
    if (lane == 31) { sWarpL[w] = mL; sWarpH[w] = mH; }
    __syncthreads();   // B3

    // ---- parallel cross-warp exclusive ----
    Map aexL = mapIdent(), aexH = mapIdent();
#pragma unroll
    for (int i = 0; i < NW - 1; i++) {
        if (i < w) {
            aexL = mapCompose(sWarpL[i], aexL);
            aexH = mapCompose(sWarpH[i], aexH);
        }
    }

    // ---- thread BT-1 publishes block aggregate immediately ----
    if (t == BT - 1) {
        Map eL = mapCompose(mL, aexL);
        Map eH = mapCompose(mH, aexH);
        __stcg(&g_agg[bid][0], make_float4(eL.a, eL.b, eL.c, eL.d));
        __stcg(&g_agg[bid][1], make_float4(eL.p, eL.q, eH.p, eH.q));
        __stcg(&g_agg[bid][2], make_float4(eH.a, eH.b, eH.c, eH.d));
        __threadfence();
        atomicExch(&g_flag[bid], 1);
    }

    // ---- parallel-window look-back (warp 0) + flag recycling ----
    if (w == 0) {
        int pred = bid - 1 - t;
        if (t < WIN && pred >= 0) {
            while (__ldcg(&g_flag[pred]) == 0) __nanosleep(64);
            __threadfence();
            sPred[t][0] = __ldcg(&g_agg[pred][0]);
            sPred[t][1] = __ldcg(&g_agg[pred][1]);
            sPred[t][2] = __ldcg(&g_agg[pred][2]);
            int R = (NBLK - 1 - pred < WIN) ? (NBLK - 1 - pred) : WIN;
            int old = atomicAdd(&g_cnt[pred], 1);
            if (old == R - 1) {
                __stcg(&g_cnt[pred], 0);
                __stcg(&g_flag[pred], 0);
            }
        }
        __syncwarp();
        if (t == 0) {
            float4 vin = make_float4(0.f, 0.f, 0.f, 0.f);
            if (bid > 0) {
                int nAvail = (bid < WIN) ? bid : WIN;
                int term = nAvail - 1;
                for (int i = 0; i < nAvail; i++) {
                    float4 fL = sPred[i][0];
                    float4 fH = sPred[i][2];
                    if (fL.x == 0.f && fL.y == 0.f && fL.z == 0.f && fL.w == 0.f &&
                        fH.x == 0.f && fH.y == 0.f && fH.z == 0.f && fH.w == 0.f) {
                        term = i;
                        break;
                    }
                }
                float4 off0 = sPred[term][1];
                float sLx = off0.x, sLy = off0.y, sHx = off0.z, sHy = off0.w;
                for (int i = term - 1; i >= 0; i--) {
                    float4 fL = sPred[i][0];
                    float4 fH = sPred[i][2];
                    float4 fo = sPred[i][1];
                    float nLx = fmaf(fL.x, sLx, fmaf(fL.y, sLy, fo.x));
                    float nLy = fmaf(fL.z, sLx, fmaf(fL.w, sLy, fo.y));
                    float nHx = fmaf(fH.x, sHx, fmaf(fH.y, sHy, fo.z));
                    float nHy = fmaf(fH.z, sHx, fmaf(fH.w, sHy, fo.w));
                    sLx = nLx; sLy = nLy; sHx = nHx; sHy = nHy;
                }
                vin = make_float4(sLx, sLy, sHx, sHy);
            }
            sVin = vin;
        }
    }
    __syncthreads();   // B4
    float4 vin = sVin;

    // thread-exclusive map within block (of composite maps)
    Map exL = mapShflUp(mL, 1);
    Map exH = mapShflUp(mH, 1);
    if (lane == 0) { exL = mapIdent(); exH = mapIdent(); }
    exL = mapCompose(exL, aexL);
    exH = mapCompose(exH, aexH);

    // init states: sub-chunk A directly; sub-chunk B = M_A(sA)
    float2 sLA = resetCk ? make_float2(0.f, 0.f) : mapApply(exL, vin.x, vin.y);
    float2 sHA = resetCk ? make_float2(0.f, 0.f) : mapApply(exH, vin.z, vin.w);
    float2 sLB, sHB;
    if (resetCk) {
        sLB = make_float2(la1, la2);
        sHB = make_float2(ha1, ha2);
    } else {
        sLB = make_float2(fmaf(e40a.x, sLA.x, fmaf(e40a.y, sLA.y, la1)),
                          fmaf(e40b.x, sLA.x, fmaf(e40b.y, sLA.y, la2)));
        sHB = make_float2(fmaf(e40a.z, sHA.x, fmaf(e40a.w, sHA.y, ha1)),
                          fmaf(e40b.z, sHA.x, fmaf(e40b.w, sHA.y, ha2)));
    }

    // ---- correction pass: two independent chains (ILP-2) ----
    if (valid) {
        u64 cdA1 = pack2(sLA.x, sHA.x), cdA2 = pack2(sLA.y, sHA.y);
        u64 cdB1 = pack2(sLB.x, sHB.x), cdB2 = pack2(sLB.y, sHB.y);
        float* cb = sbuf + t * CHUNK;
#pragma unroll
        for (int k = 0; k < SUBA; k += 4) {
            float4 ya = *reinterpret_cast<const float4*>(cb + k);
            float4 yb = *reinterpret_cast<const float4*>(cb + SUBA + k);
            float4 oa, ob;
            CSTEP2S(ya.x, oa.x, cdA1, cdA2);
            CSTEP2S(yb.x, ob.x, cdB1, cdB2);
            CSTEP2S(ya.y, oa.y, cdA1, cdA2);
            CSTEP2S(yb.y, ob.y, cdB1, cdB2);
            CSTEP2S(ya.z, oa.z, cdA1, cdA2);
            CSTEP2S(yb.z, ob.z, cdB1, cdB2);
            CSTEP2S(ya.w, oa.w, cdA1, cdA2);
            CSTEP2S(yb.w, ob.w, cdB1, cdB2);
            *reinterpret_cast<float4*>(cb + k) = oa;
            *reinterpret_cast<float4*>(cb + SUBA + k) = ob;
        }
        float4 yb = *reinterpret_cast<const float4*>(cb + 2 * SUBA);
        float4 ob;
        CSTEP2S(yb.x, ob.x, cdB1, cdB2);
        CSTEP2S(yb.y, ob.y, cdB1, cdB2);
        CSTEP2S(yb.z, ob.z, cdB1, cdB2);
        CSTEP2S(yb.w, ob.w, cdB1, cdB2);
        *reinterpret_cast<float4*>(cb + 2 * SUBA) = ob;
    }
    __syncthreads();   // B5

    // ---- coalesced store ----
    float4* og4 = (float4*)out;
    if (fullBlk) {
#pragma unroll
        for (int i = 0; i < F4PB / BT; i++)
            og4[base4 + t + (size_t)i * BT] = s4[t + i * BT];
    } else {
#pragma unroll
        for (int i = 0; i < F4PB / BT; i++) {
            size_t idx = base4 + t + (size_t)i * BT;
            if (idx < TOTAL_F4) og4[idx] = s4[t + i * BT];
        }
    }
}

extern "C" void kernel_launch(void* const* d_in, const int* in_sizes, int n_in,
                              void* d_out, int out_size) {
    const float* audio = (const float*)d_in[0];
    const int*   sr    = (const int*)d_in[1];
    const float* cl    = (const float*)d_in[2];
    const float* ch    = (const float*)d_in[3];
    float* out = (float*)d_out;

    fused_kernel<<<NBLK, BT>>>(audio, out, sr, cl, ch);
}

// round 17
// speedup vs baseline: 1.1463x; 1.1463x over previous
#include <cuda_runtime.h>
#include <math.h>

#define T_LEN      220500
#define NCH        64
#define CHUNK      84
#define NCHUNK_CH  2625                // 220500 / 84
#define NCHUNK_TOT 168000              // 64 * 2625
#define TOTAL_F4   3528000             // 14,112,000 / 4
#define BT         128
#define NW         (BT / 32)
#define TILE       (BT * CHUNK)        // 10752 floats = 43008 B
#define F4PB       (TILE / 4)          // 2688
#define NBLK       ((NCHUNK_TOT + BT - 1) / BT)   // 1313
#define WIN        21                  // reset-block gap is exactly 20-21

typedef unsigned long long u64;

// ---- packed f32x2 helpers (sm_103a FFMA2 path) ----
__device__ __forceinline__ u64 fma2(u64 a, u64 b, u64 c) {
    u64 d; asm("fma.rn.f32x2 %0, %1, %2, %3;" : "=l"(d) : "l"(a), "l"(b), "l"(c)); return d;
}
__device__ __forceinline__ u64 mul2(u64 a, u64 b) {
    u64 d; asm("mul.rn.f32x2 %0, %1, %2;" : "=l"(d) : "l"(a), "l"(b)); return d;
}
__device__ __forceinline__ u64 pack2(float lo, float hi) {
    u64 d; asm("mov.b64 %0, {%1, %2};" : "=l"(d) : "f"(lo), "f"(hi)); return d;
}
__device__ __forceinline__ void unpack2(u64 v, float& lo, float& hi) {
    asm("mov.b64 {%0, %1}, %2;" : "=f"(lo), "=f"(hi) : "l"(v));
}

// published per-block aggregate: [0]=(La,Lb,Lc,Ld) [1]=(Lp,Lq,Hp,Hq) [2]=(Ha,Hb,Hc,Hd)
__device__ float4 g_agg[NBLK][3];
__device__ int    g_flag[NBLK];    // statically zero-init; self-resetting per replay
__device__ int    g_cnt[NBLK];     // read-counters; self-resetting per replay

struct Map { float a, b, c, d, p, q; };   // s -> [a b; c d] s + (p,q)

__device__ __forceinline__ Map mapIdent() { Map m = {1.f,0.f,0.f,1.f,0.f,0.f}; return m; }
// hi applied AFTER lo
__device__ __forceinline__ Map mapCompose(const Map& hi, const Map& lo) {
    Map r;
    r.a = fmaf(hi.a, lo.a, hi.b * lo.c);
    r.b = fmaf(hi.a, lo.b, hi.b * lo.d);
    r.c = fmaf(hi.c, lo.a, hi.d * lo.c);
    r.d = fmaf(hi.c, lo.b, hi.d * lo.d);
    r.p = fmaf(hi.a, lo.p, fmaf(hi.b, lo.q, hi.p));
    r.q = fmaf(hi.c, lo.p, fmaf(hi.d, lo.q, hi.q));
    return r;
}
__device__ __forceinline__ float2 mapApply(const Map& m, float vx, float vy) {
    return make_float2(fmaf(m.a, vx, fmaf(m.b, vy, m.p)),
                       fmaf(m.c, vx, fmaf(m.d, vy, m.q)));
}
__device__ __forceinline__ Map mapShflUp(const Map& m, int d) {
    Map r;
    r.a = __shfl_up_sync(0xffffffffu, m.a, d);
    r.b = __shfl_up_sync(0xffffffffu, m.b, d);
    r.c = __shfl_up_sync(0xffffffffu, m.c, d);
    r.d = __shfl_up_sync(0xffffffffu, m.d, d);
    r.p = __shfl_up_sync(0xffffffffu, m.p, d);
    r.q = __shfl_up_sync(0xffffffffu, m.q, d);
    return r;
}

// packed biquad step (both filters in one f32x2 lane pair): y0 = yL - yH
#define BSTEP2(xk, ok) {                                         \
    u64 xk2 = pack2((xk), (xk));                                 \
    u64 ff  = fma2(cb0, xk2, fma2(cb1, xm1p, mul2(cb2, xm2p))); \
    u64 yy  = fma2(cn1, s1p, fma2(cn2, s2p, ff));                \
    float yL, yH; unpack2(yy, yL, yH);                           \
    (ok) = yL - yH;                                              \
    s2p = s1p; s1p = yy; xm2p = xm1p; xm1p = xk2; }

// packed homogeneous correction step: y = y0 + c - d
#define CSTEP2(y0v, ov) {                                        \
    u64 cd = fma2(cn1, cd1, mul2(cn2, cd2));                     \
    float cc, dd; unpack2(cd, cc, dd);                           \
    (ov) = ((y0v) + cc) - dd;                                    \
    cd2 = cd1; cd1 = cd; }

__global__ __launch_bounds__(BT, 5)
void fused_kernel(const float* __restrict__ x, float* __restrict__ out,
                  const int* __restrict__ sr_p,
                  const float* __restrict__ cl_p,
                  const float* __restrict__ ch_p) {
    __shared__ float  sbuf[TILE];
    __shared__ float  scoef[10];
    __shared__ float4 sAE[2];            // [0]=(uL,vL,uH,vH)@n=END-1  [1]=@n=END-2
    __shared__ Map    sWarpL[NW], sWarpH[NW], sExclL[NW], sExclH[NW];
    __shared__ float4 sPred[WIN][3];
    __shared__ float4 sVin;

    int t   = threadIdx.x;
    int bid = blockIdx.x;
    bool fullBlk = (bid < NBLK - 1);     // all but last block are fully valid

    // ---- stage tile coalesced (streaming loads — consumed once) ----
    size_t base4 = (size_t)bid * F4PB;
    const float4* xg4 = (const float4*)x;
    float4* s4 = (float4*)sbuf;
    if (fullBlk) {
#pragma unroll
        for (int i = 0; i < F4PB / BT; i++)
            s4[t + i * BT] = __ldcs(xg4 + base4 + t + (size_t)i * BT);
    } else {
#pragma unroll
        for (int i = 0; i < F4PB / BT; i++) {
            size_t idx = base4 + t + (size_t)i * BT;
            if (idx < TOTAL_F4) s4[t + i * BT] = __ldcs(xg4 + idx);
        }
    }

    // ---- thread 0: coefficients ----
    if (t == 0) {
        int iv = *sr_p;
        float sr = (iv > 0 && iv < 100000000) ? (float)iv : __int_as_float(iv);
        const float Q = 0.707f;
        {
            float w0 = 2.0f * 3.14159265358979323846f * (*cl_p) / sr;
            float c  = cosf(w0);
            float al = sinf(w0) / (2.0f * Q);
            float a0 = 1.0f + al;
            scoef[0] = ((1.0f - c) * 0.5f) / a0;
            scoef[1] = (1.0f - c) / a0;
            scoef[2] = scoef[0];
            scoef[3] = (-2.0f * c) / a0;
            scoef[4] = (1.0f - al) / a0;
        }
        {
            float w0 = 2.0f * 3.14159265358979323846f * (*ch_p) / sr;
            float c  = cosf(w0);
            float al = sinf(w0) / (2.0f * Q);
            float a0 = 1.0f + al;
            scoef[5] = ((1.0f + c) * 0.5f) / a0;
            scoef[6] = -(1.0f + c) / a0;
            scoef[7] = scoef[5];
            scoef[8] = (-2.0f * c) / a0;
            scoef[9] = (1.0f - al) / a0;
        }
    }
    __syncthreads();

    float bL0 = scoef[0], bL1 = scoef[1], bL2 = scoef[2];
    float nL1 = -scoef[3], nL2 = -scoef[4];
    float bH0 = scoef[5], bH1 = scoef[6], bH2 = scoef[7];
    float nH1 = -scoef[8], nH2 = -scoef[9];

    // packed coefficient pairs (L in lane0, H in lane1)
    u64 cb0 = pack2(bL0, bH0), cb1 = pack2(bL1, bH1), cb2 = pack2(bL2, bH2);
    u64 cn1 = pack2(nL1, nH1), cn2 = pack2(nL2, nH2);

    int  g       = bid * BT + t;
    bool valid   = g < NCHUNK_TOT;
    bool resetCk = valid && (g % NCHUNK_CH) == 0;   // chunk is channel start

    // FIR history — must be read by ALL threads before pass A overwrites smem
    float hx1 = 0.f, hx2 = 0.f;
    if (valid && !resetCk) {
        if (t == 0) {
            size_t s0 = (size_t)g * CHUNK;
            hx1 = x[s0 - 1];
            hx2 = x[s0 - 2];
        } else {
            hx1 = sbuf[t * CHUNK - 1];
            hx2 = sbuf[t * CHUNK - 2];
        }
    }
    __syncthreads();   // history reads complete before in-place y0 writes

    // ---- A^CHUNK end states (threads 0-3, one homogeneous basis each) ----
    if (t < 4) {
        float na1 = (t < 2) ? nL1 : nH1;
        float na2 = (t < 2) ? nL2 : nH2;
        float y1 = (t & 1) ? 0.f : 1.f;
        float y2 = (t & 1) ? 1.f : 0.f;
#pragma unroll 1
        for (int n = 0; n < CHUNK; n++) {
            float y = fmaf(na1, y1, na2 * y2);
            y2 = y1; y1 = y;
        }
        ((float*)&sAE[0])[t] = y1;   // y[CHUNK-1]
        ((float*)&sAE[1])[t] = y2;   // y[CHUNK-2]
    }

    // ---- pass A: zero-init packed recurrence, write y0 in place ----
    float l1, l2, h1, h2;
    {
        u64 s1p = pack2(0.f, 0.f), s2p = s1p;
        u64 xm1p = pack2(hx1, hx1), xm2p = pack2(hx2, hx2);
        if (valid) {
            float* cb = sbuf + t * CHUNK;
#pragma unroll 7
            for (int k = 0; k < CHUNK; k += 4) {
                float4 xv = *reinterpret_cast<const float4*>(cb + k);
                float4 ov;
                BSTEP2(xv.x, ov.x);
                BSTEP2(xv.y, ov.y);
                BSTEP2(xv.z, ov.z);
                BSTEP2(xv.w, ov.w);
                *reinterpret_cast<float4*>(cb + k) = ov;
            }
        }
        unpack2(s1p, l1, h1);
        unpack2(s2p, l2, h2);
    }
    __syncthreads();

    float4 tE1 = sAE[0];
    float4 tE2 = sAE[1];

    // ---- per-chunk affine maps (interleaved L/H scan) ----
    Map mL, mH;
    if (!valid) { mL = mapIdent(); mH = mapIdent(); }
    else if (resetCk) {
        mL.a = mL.b = mL.c = mL.d = 0.f; mL.p = l1; mL.q = l2;
        mH.a = mH.b = mH.c = mH.d = 0.f; mH.p = h1; mH.q = h2;
    } else {
        mL.a = tE1.x; mL.b = tE1.y; mL.c = tE2.x; mL.d = tE2.y; mL.p = l1; mL.q = l2;
        mH.a = tE1.z; mH.b = tE1.w; mH.c = tE2.z; mH.d = tE2.w; mH.p = h1; mH.q = h2;
    }

    int lane = t & 31, w = t >> 5;
#pragma unroll
    for (int off = 1; off < 32; off <<= 1) {
        Map pL = mapShflUp(mL, off);
        Map pH = mapShflUp(mH, off);
        if (lane >= off) { mL = mapCompose(mL, pL); mH = mapCompose(mH, pH); }
    }
    if (lane == 31) { sWarpL[w] = mL; sWarpH[w] = mH; }
    __syncthreads();

    // ---- block aggregate + IMMEDIATE publish ----
    if (t == 0) {
        Map eL = mapIdent(), eH = mapIdent();
#pragma unroll
        for (int i = 0; i < NW; i++) {
            sExclL[i] = eL; sExclH[i] = eH;
            eL = mapCompose(sWarpL[i], eL);
            eH = mapCompose(sWarpH[i], eH);
        }
        __stcg(&g_agg[bid][0], make_float4(eL.a, eL.b, eL.c, eL.d));
        __stcg(&g_agg[bid][1], make_float4(eL.p, eL.q, eH.p, eH.q));
        __stcg(&g_agg[bid][2], make_float4(eH.a, eH.b, eH.c, eH.d));
        __threadfence();
        atomicExch(&g_flag[bid], 1);
    }

    // ---- parallel-window look-back (warp 0) + flag recycling ----
    if (w == 0) {
        int pred = bid - 1 - t;
        if (t < WIN && pred >= 0) {
            while (__ldcg(&g_flag[pred]) == 0) __nanosleep(64);
            __threadfence();
            sPred[t][0] = __ldcg(&g_agg[pred][0]);
            sPred[t][1] = __ldcg(&g_agg[pred][1]);
            sPred[t][2] = __ldcg(&g_agg[pred][2]);
            // flag recycling: last of R readers resets flag+cnt for next replay
            int R = (NBLK - 1 - pred < WIN) ? (NBLK - 1 - pred) : WIN;
            int old = atomicAdd(&g_cnt[pred], 1);
            if (old == R - 1) {
                __stcg(&g_cnt[pred], 0);
                __stcg(&g_flag[pred], 0);
            }
        }
        __syncwarp();
        if (t == 0) {
            float4 vin = make_float4(0.f, 0.f, 0.f, 0.f);
            if (bid > 0) {
                int nAvail = (bid < WIN) ? bid : WIN;
                int term = nAvail - 1;
                for (int i = 0; i < nAvail; i++) {
                    float4 fL = sPred[i][0];
                    float4 fH = sPred[i][2];
                    if (fL.x == 0.f && fL.y == 0.f && fL.z == 0.f && fL.w == 0.f &&
                        fH.x == 0.f && fH.y == 0.f && fH.z == 0.f && fH.w == 0.f) {
                        term = i;
                        break;
                    }
                }
                float4 off0 = sPred[term][1];
                float sLx = off0.x, sLy = off0.y, sHx = off0.z, sHy = off0.w;
                for (int i = term - 1; i >= 0; i--) {
                    float4 fL = sPred[i][0];
                    float4 fH = sPred[i][2];
                    float4 fo = sPred[i][1];
                    float nLx = fmaf(fL.x, sLx, fmaf(fL.y, sLy, fo.x));
                    float nLy = fmaf(fL.z, sLx, fmaf(fL.w, sLy, fo.y));
                    float nHx = fmaf(fH.x, sHx, fmaf(fH.y, sHy, fo.z));
                    float nHy = fmaf(fH.z, sHx, fmaf(fH.w, sHy, fo.w));
                    sLx = nLx; sLy = nLy; sHx = nHx; sHy = nHy;
                }
                vin = make_float4(sLx, sLy, sHx, sHy);
            }
            sVin = vin;
        }
    }
    __syncthreads();
    float4 vin = sVin;

    // thread-exclusive map within block
    Map exL = mapShflUp(mL, 1);
    Map exH = mapShflUp(mH, 1);
    if (lane == 0) { exL = mapIdent(); exH = mapIdent(); }
    exL = mapCompose(exL, sExclL[w]);
    exH = mapCompose(exH, sExclH[w]);

    // exact initial state for this chunk
    float2 sL = resetCk ? make_float2(0.f, 0.f) : mapApply(exL, vin.x, vin.y);
    float2 sH = resetCk ? make_float2(0.f, 0.f) : mapApply(exH, vin.z, vin.w);

    // ---- correction pass (packed): y = y0 + c - d ----
    if (valid) {
        u64 cd1 = pack2(sL.x, sH.x);
        u64 cd2 = pack2(sL.y, sH.y);
        float* cb = sbuf + t * CHUNK;
#pragma unroll 7
        for (int k = 0; k < CHUNK; k += 4) {
            float4 yv = *reinterpret_cast<const float4*>(cb + k);
            float4 ov;
            CSTEP2(yv.x, ov.x);
            CSTEP2(yv.y, ov.y);
            CSTEP2(yv.z, ov.z);
            CSTEP2(yv.w, ov.w);
            *reinterpret_cast<float4*>(cb + k) = ov;
        }
    }
    __syncthreads();

    // ---- coalesced store (L1-bypass; output never re-read) ----
    float4* og4 = (float4*)out;
    if (fullBlk) {
#pragma unroll
        for (int i = 0; i < F4PB / BT; i++)
            __stcg(og4 + base4 + t + (size_t)i * BT, s4[t + i * BT]);
    } else {
#pragma unroll
        for (int i = 0; i < F4PB / BT; i++) {
            size_t idx = base4 + t + (size_t)i * BT;
            if (idx < TOTAL_F4) __stcg(og4 + idx, s4[t + i * BT]);
        }
    }
}

extern "C" void kernel_launch(void* const* d_in, const int* in_sizes, int n_in,
                              void* d_out, int out_size) {
    const float* audio = (const float*)d_in[0];
    const int*   sr    = (const int*)d_in[1];
    const float* cl    = (const float*)d_in[2];
    const float* ch    = (const float*)d_in[3];
    float* out = (float*)d_out;

    fused_kernel<<<NBLK, BT>>>(audio, out, sr, cl, ch);
}